// round 8
// baseline (speedup 1.0000x reference)
#include <cuda_runtime.h>
#include <cuda_fp16.h>
#include <math.h>
#include <stdint.h>

#define BATCH 16
#define SEQ   4096
#define DIM   512
#define CH    64
#define NC    64

#define MAX_LR_C    0.2f
#define MIN_DECAY_C 0.5f
#define MAX_NORM_C  30.0f
#define NORM_EPS_C  1e-5f

// ---------------- scratch (static device globals) ----------------
__device__ float g_kmean[BATCH*NC*DIM];
__device__ float g_u[BATCH*NC*DIM];
__device__ float g_EF[2*BATCH*NC*DIM];
__device__ float g_KU[BATCH*NC*NC];
__device__ float g_KK[BATCH*NC*NC];
__device__ float g_gate[BATCH*NC];
__device__ float g_Cout[BATCH*NC];
__device__ float g_W[BATCH*NC*NC];
__device__ float g_Err2[BATCH*NC*DIM];          // [b][t][i]
__device__ float g_Cend[BATCH];
__device__ float g_Dend[BATCH*NC];
__device__ float g_fro2[1];

__device__ __half g_xF[(long)BATCH*SEQ*DIM];
__device__ __half g_Y0F[(long)BATCH*SEQ*DIM];   // fp16 Y0 = x @ M0^T
__device__ __half g_ukF[2*BATCH*NC*DIM];        // u rows then kmean rows
__device__ __half g_M0F[DIM*DIM];
__device__ __half g_w1F[DIM*DIM];
__device__ __half g_w2F[DIM*DIM];
__device__ __half g_errF[BATCH*DIM*NC];         // [b][i][j]
__device__ __half g_TmF[(long)BATCH*SEQ*NC];
__device__ __half g_outF[(long)BATCH*SEQ*DIM];
__device__ __half g_hidF[(long)BATCH*SEQ*DIM];

// ---------------- PTX helpers ----------------
__device__ __forceinline__ uint32_t smem_u32(const void* p) {
    uint32_t a;
    asm("{ .reg .u64 t; cvta.to.shared.u64 t, %1; cvt.u32.u64 %0, t; }" : "=r"(a) : "l"(p));
    return a;
}
#define CP16(dst, src) \
    asm volatile("cp.async.cg.shared.global [%0], [%1], 16;" :: "r"(dst), "l"(src) : "memory")
#define CPCOMMIT() asm volatile("cp.async.commit_group;" ::: "memory")
#define CPWAIT(n)  asm volatile("cp.async.wait_group %0;" :: "n"(n) : "memory")

__device__ __forceinline__ void ldsm4(uint32_t* r, uint32_t addr) {
    asm volatile("ldmatrix.sync.aligned.m8n8.x4.shared.b16 {%0,%1,%2,%3}, [%4];"
        : "=r"(r[0]), "=r"(r[1]), "=r"(r[2]), "=r"(r[3]) : "r"(addr));
}
__device__ __forceinline__ void mma16816(float* c, const uint32_t* a, const uint32_t* b) {
    asm volatile(
        "mma.sync.aligned.m16n8k16.row.col.f32.f16.f16.f32 "
        "{%0,%1,%2,%3}, {%4,%5,%6,%7}, {%8,%9}, {%0,%1,%2,%3};"
        : "+f"(c[0]), "+f"(c[1]), "+f"(c[2]), "+f"(c[3])
        : "r"(a[0]), "r"(a[1]), "r"(a[2]), "r"(a[3]), "r"(b[0]), "r"(b[1]));
}

// =====================================================================
// fp16 tensor-core GEMM: C[M,N] = A[M,K] @ B[N,K]^T
// BM=128, BK=64, BN template {64,128}. 8 warps 4(M)x2(N).
// 3-stage cp.async ring, ONE barrier per chunk, 2 CTAs/SM.
// epi: 0 C=acc | 2 OF=silu(acc) | 4 OF=acc*Wrow
//      6 OF=half(acc + R[t]*Pf) | 7 C=acc+Pf | 8 OF=half(acc)
// =====================================================================
#define PITCH 72

template<int BNv>
__global__ __launch_bounds__(256, 2) void tgemm(
    const __half* __restrict__ A, const __half* __restrict__ B,
    float* __restrict__ C, __half* __restrict__ OF,
    const __half* __restrict__ Pf, const float* __restrict__ Rvec, const float* __restrict__ Wm,
    int N, int K,
    long sA, long sB, long sC, long sO, long sP, long sR, long sW, int epi)
{
    constexpr int NT   = BNv / 16;
    constexpr int AOFF = 128 * PITCH * 2;
    constexpr int SS   = AOFF + BNv * PITCH * 2;

    extern __shared__ char smraw[];
    const uint32_t sbase = smem_u32(smraw);

    const int tid = threadIdx.x;
    const int wid = tid >> 5, lane = tid & 31;
    const int wm = wid >> 1, wn = wid & 1;
    const int bx = blockIdx.x, by = blockIdx.y, bz = blockIdx.z;
    const int nk = K >> 6;

    const __half* Ab = A + bz*sA + (long)(by*128)*K;
    const __half* Bb = B + bz*sB + (long)(bx*BNv)*K;

    auto stage = [&](int c) {
        const int s = c % 3;
        const uint32_t st = sbase + s*SS;
        const int koff = c*64;
        #pragma unroll
        for (int j = 0; j < 4; ++j) {
            int i = tid + 256*j;
            int r = i >> 3, v = i & 7;
            CP16(st + (uint32_t)(r*PITCH + v*8)*2, Ab + (long)r*K + koff + v*8);
        }
        #pragma unroll
        for (int j = 0; j < BNv/32; ++j) {
            int i = tid + 256*j;
            int r = i >> 3, v = i & 7;
            CP16(st + AOFF + (uint32_t)(r*PITCH + v*8)*2, Bb + (long)r*K + koff + v*8);
        }
        CPCOMMIT();
    };

    float acc[2][NT][4];
    #pragma unroll
    for (int mt = 0; mt < 2; ++mt)
        #pragma unroll
        for (int nt = 0; nt < NT; ++nt)
            #pragma unroll
            for (int q = 0; q < 4; ++q) acc[mt][nt][q] = 0.f;

    const int arow  = wm*32 + (lane & 15);
    const int acolh = (lane >> 4) * 8;
    const int brow  = wn*(BNv/2) + (lane & 7) + ((lane & 16) ? 8 : 0);
    const int bcolh = (lane & 8) ? 8 : 0;

    uint32_t ah[2][4], bfr[NT][2];

    stage(0);
    if (nk > 1) stage(1);
    for (int c = 0; c < nk; ++c) {
        if (c + 1 < nk) CPWAIT(1); else CPWAIT(0);
        __syncthreads();   // also guarantees all warps finished reading slot (c+2)%3 last round
        if (c + 2 < nk) stage(c + 2);

        const uint32_t st  = sbase + (c % 3)*SS;
        const uint32_t aB = st, bB = st + AOFF;

        #pragma unroll
        for (int kk = 0; kk < 4; ++kk) {
            #pragma unroll
            for (int mt = 0; mt < 2; ++mt) {
                uint32_t off = (uint32_t)((arow + mt*16)*PITCH + kk*16 + acolh)*2;
                ldsm4(ah[mt], aB + off);
            }
            #pragma unroll
            for (int p = 0; p < NT/2; ++p) {
                uint32_t off = (uint32_t)((brow + p*16)*PITCH + kk*16 + bcolh)*2;
                uint32_t r4[4];
                ldsm4(r4, bB + off);
                bfr[2*p][0]=r4[0]; bfr[2*p][1]=r4[1];
                bfr[2*p+1][0]=r4[2]; bfr[2*p+1][1]=r4[3];
            }
            #pragma unroll
            for (int mt = 0; mt < 2; ++mt)
                #pragma unroll
                for (int nt = 0; nt < NT; ++nt)
                    mma16816(acc[mt][nt], ah[mt], bfr[nt]);
        }
    }

    // ---------------- epilogue ----------------
    const int g2 = lane >> 2, tq = lane & 3;
    #pragma unroll
    for (int mt = 0; mt < 2; ++mt)
        #pragma unroll
        for (int rh = 0; rh < 2; ++rh) {
            const long mg = (long)by*128 + wm*32 + mt*16 + rh*8 + g2;
            float rs = 0.f;
            if (epi == 6) rs = Rvec[bz*sR + (mg >> 6)];
            #pragma unroll
            for (int nt = 0; nt < NT; ++nt) {
                const int col = bx*BNv + wn*(BNv/2) + nt*8 + 2*tq;
                float v0 = acc[mt][nt][rh*2 + 0];
                float v1 = acc[mt][nt][rh*2 + 1];
                const long cofs = mg*(long)N + col;
                if (epi == 6) {
                    __half2 q = *(const __half2*)(Pf + bz*sP + cofs);
                    v0 += rs*__half2float(q.x); v1 += rs*__half2float(q.y);
                } else if (epi == 2) {
                    v0 = v0 / (1.f + expf(-v0));
                    v1 = v1 / (1.f + expf(-v1));
                } else if (epi == 7) {
                    __half2 q = *(const __half2*)(Pf + bz*sP + cofs);
                    v0 += __half2float(q.x); v1 += __half2float(q.y);
                } else if (epi == 4) {
                    const float* wr = Wm + bz*sW + (mg >> 6)*NC + col;
                    v0 *= wr[0]; v1 *= wr[1];
                }
                if (epi == 0 || epi == 7)
                    *(float2*)(C + bz*sC + cofs) = make_float2(v0, v1);
                if (epi == 2 || epi == 4 || epi == 6 || epi == 8) {
                    __half2 hh;
                    hh.x = __float2half_rn(v0);
                    hh.y = __float2half_rn(v1);
                    *(__half2*)(OF + bz*sO + cofs) = hh;
                }
            }
        }
}

template<int BNv>
static void launch_tgemm(const __half* A, const __half* B,
                         float* C, __half* OF,
                         const __half* Pf, const float* Rvec, const float* Wm,
                         int M, int N, int K, int batch,
                         long sA, long sB, long sC, long sO, long sP, long sR, long sW, int epi)
{
    int smb = 3 * (128*PITCH*2 + BNv*PITCH*2);
    cudaFuncSetAttribute(tgemm<BNv>, cudaFuncAttributeMaxDynamicSharedMemorySize, smb);
    dim3 g(N/BNv, M/128, batch);
    tgemm<BNv><<<g, 256, smb>>>(A, B, C, OF, Pf, Rvec, Wm,
                                N, K, sA, sB, sC, sO, sP, sR, sW, epi);
}

// ---------------- K0: ||M0||_F^2 ----------------
__global__ void frob_kernel(const float* __restrict__ M0) {
    __shared__ float sbuf[32];
    float s = 0.f;
    for (int i = threadIdx.x; i < DIM*DIM; i += blockDim.x) { float v = M0[i]; s += v*v; }
    #pragma unroll
    for (int o = 16; o; o >>= 1) s += __shfl_down_sync(0xffffffffu, s, o);
    int w = threadIdx.x >> 5, l = threadIdx.x & 31;
    if (l == 0) sbuf[w] = s;
    __syncthreads();
    if (w == 0) {
        s = (l < (int)(blockDim.x >> 5)) ? sbuf[l] : 0.f;
        #pragma unroll
        for (int o = 16; o; o >>= 1) s += __shfl_down_sync(0xffffffffu, s, o);
        if (l == 0) g_fro2[0] = s;
    }
}

// ---------------- K1: per-chunk kmean, u, gate + x fp16 ----------------
__global__ __launch_bounds__(256) void prep_kernel(const float* __restrict__ x,
                                                   const float* __restrict__ gate_w,
                                                   const float* __restrict__ gate_b) {
    int bt = blockIdx.x;
    const float* chunk = x + (long)bt * CH * DIM;
    __shared__ float rinv[CH];
    __shared__ float sred[8];
    int tid = threadIdx.x, w = tid >> 5, l = tid & 31;

    for (int r = w; r < CH; r += 8) {
        const float* row = chunk + (long)r * DIM;
        float s = 0.f;
        for (int i = l; i < DIM; i += 32) { float v = row[i]; s += v*v; }
        #pragma unroll
        for (int o = 16; o; o >>= 1) s += __shfl_down_sync(0xffffffffu, s, o);
        if (l == 0) rinv[r] = 1.f / fmaxf(sqrtf(s), NORM_EPS_C);
    }
    __syncthreads();

    float gpart = 0.f;
    for (int i = tid; i < DIM; i += 256) {
        float sx = 0.f, sk = 0.f;
        #pragma unroll 4
        for (int r = 0; r < CH; r++) {
            long gi = (long)bt*CH*DIM + (long)r*DIM + i;
            float v = x[gi];
            g_xF[gi] = __float2half_rn(v);
            sx += v;
            sk += v * rinv[r];
        }
        float km = sk * (1.f/CH);
        float uv = sx * (1.f/CH) - km;
        long ru = (long)bt*DIM + i;
        long rk = (long)(BATCH*NC + bt)*DIM + i;
        g_kmean[ru] = km;
        g_u[ru]     = uv;
        g_ukF[ru] = __float2half_rn(uv);
        g_ukF[rk] = __float2half_rn(km);
        gpart += km * gate_w[i];
    }
    #pragma unroll
    for (int o = 16; o; o >>= 1) gpart += __shfl_down_sync(0xffffffffu, gpart, o);
    if (l == 0) sred[w] = gpart;
    __syncthreads();
    if (tid == 0) {
        float g = 0.f;
        #pragma unroll
        for (int k = 0; k < 8; k++) g += sred[k];
        g_gate[bt] = 1.f / (1.f + expf(-(g + gate_b[0])));
    }
}

// ---------------- K2: Gram matrices ----------------
__global__ __launch_bounds__(256) void gram_kernel() {
    int t = blockIdx.x, b = blockIdx.y;
    __shared__ float su[DIM], sk[DIM];
    int tid = threadIdx.x;
    for (int i = tid; i < DIM; i += 256) {
        su[i] = g_u[((long)b*NC + t)*DIM + i];
        sk[i] = g_kmean[((long)b*NC + t)*DIM + i];
    }
    __syncthreads();
    int w = tid >> 5, l = tid & 31;
    for (int j = w; j < NC; j += 8) {
        const float* kj = &g_kmean[((long)b*NC + j)*DIM];
        float pu = 0.f, pk = 0.f;
        for (int i = l; i < DIM; i += 32) {
            float kv = kj[i];
            pu += kv * su[i];
            pk += kv * sk[i];
        }
        #pragma unroll
        for (int o = 16; o; o >>= 1) {
            pu += __shfl_down_sync(0xffffffffu, pu, o);
            pk += __shfl_down_sync(0xffffffffu, pk, o);
        }
        if (l == 0) {
            g_KU[((long)b*NC + t)*NC + j] = pu;
            g_KK[((long)b*NC + t)*NC + j] = pk;
        }
    }
}

// ---------------- K5: sequential scan ----------------
__global__ __launch_bounds__(512) void scan_kernel(const float* __restrict__ eta_raw,
                                                   const float* __restrict__ alpha_raw) {
    int b = blockIdx.x;
    int tid = threadIdx.x;
    __shared__ float sD[NC], swE[NC], swM[NC];
    __shared__ float sred[64];
    __shared__ float sC, sFro2, sSA, sSD;

    if (tid == 0) { sC = 1.f; sFro2 = g_fro2[0]; }
    if (tid < NC) sD[tid] = 0.f;
    float eta   = (1.f / (1.f + expf(-eta_raw[0]))) * MAX_LR_C;
    float alpha = MIN_DECAY_C + (1.f / (1.f + expf(-alpha_raw[0]))) * (1.f - MIN_DECAY_C);
    float* errBase = &g_Err2[(long)b*NC*DIM + tid];
    __syncthreads();

    for (int t = 0; t < NC; t++) {
        long btn = (long)(b*NC + t)*NC;
        if (tid < NC) {
            float Dv = sD[tid];
            bool act = tid < t;
            g_W[btn + tid] = act ? Dv : 0.f;
            swE[tid] = act ? Dv * g_KU[btn + tid] : 0.f;
            swM[tid] = act ? Dv * g_KK[btn + tid] : 0.f;
        }
        if (tid == 0) g_Cout[b*NC + t] = sC;
        __syncthreads();

        float C = sC;
        float e  = C * g_EF[(long)(b*NC + t)*DIM + tid];
        float mk = C * g_EF[(long)(BATCH*NC + b*NC + t)*DIM + tid];
        for (int j = 0; j < t; j++) {
            float er = errBase[(long)j*DIM];
            e  += swE[j] * er;
            mk += swM[j] * er;
        }
        errBase[(long)t*DIM] = e;

        float r1 = e * mk, r2 = e * e;
        #pragma unroll
        for (int o = 16; o; o >>= 1) {
            r1 += __shfl_down_sync(0xffffffffu, r1, o);
            r2 += __shfl_down_sync(0xffffffffu, r2, o);
        }
        int w = tid >> 5, l = tid & 31;
        __syncthreads();
        if (l == 0) { sred[w] = r1; sred[32 + w] = r2; }
        __syncthreads();
        if (tid == 0) {
            float edm = 0.f, en2 = 0.f;
            #pragma unroll
            for (int k = 0; k < 16; k++) { edm += sred[k]; en2 += sred[32 + k]; }
            float g = g_gate[b*NC + t];
            float a = g*alpha + 1.f - g;
            float d = g*eta;
            float ktt = g_KK[btn + t];
            float fro2 = a*a*sFro2 + 2.f*a*d*edm + d*d*en2*ktt;
            float fro = sqrtf(fro2);
            float s = fminf(MAX_NORM_C / (fro + 1e-6f), 1.f);
            sSA = s*a; sSD = s*d;
            sFro2 = s*s*fro2;
            sC = sC * s * a;
        }
        __syncthreads();
        if (tid < t)  sD[tid] *= sSA;
        if (tid == t) sD[tid]  = sSD;
        __syncthreads();
    }
    if (tid == 0) g_Cend[b] = sC;
    if (tid < NC) g_Dend[b*NC + tid] = sD[tid];
}

// ---------------- transpose + fp16: Err2[b][t][i] -> errF[b][i][j] ----------------
__global__ void errsplit_kernel() {
    __shared__ float tile[32][33];
    int b  = blockIdx.z;
    int i0 = blockIdx.x * 32;
    int j0 = blockIdx.y * 32;
    int tx = threadIdx.x, ty = threadIdx.y;
    for (int jj = ty; jj < 32; jj += 8)
        tile[jj][tx] = g_Err2[((long)b*NC + j0 + jj)*DIM + i0 + tx];
    __syncthreads();
    for (int ii = ty; ii < 32; ii += 8) {
        float v = tile[tx][ii];
        long o = ((long)b*DIM + i0 + ii)*NC + j0 + tx;
        g_errF[o] = __float2half_rn(v);
    }
}

// ---------------- fp32 -> fp16 ----------------
__global__ void conv_kernel(const float* __restrict__ s, __half* __restrict__ F, long n4) {
    long i = (long)blockIdx.x * 256 + threadIdx.x;
    if (i >= n4) return;
    float4 x = ((const float4*)s)[i];
    union { __half a[4]; uint2 u; } p;
    p.a[0] = __float2half_rn(x.x);
    p.a[1] = __float2half_rn(x.y);
    p.a[2] = __float2half_rn(x.z);
    p.a[3] = __float2half_rn(x.w);
    ((uint2*)F)[i] = p.u;
}

// ---------------- M_final ----------------
__global__ __launch_bounds__(256) void mfinal_kernel(const float* __restrict__ M0,
                                                     float* __restrict__ out) {
    int og = blockIdx.x;
    int b  = blockIdx.y;
    int tid = threadIdx.x;
    __shared__ float wsm[8][NC];
    for (int s = tid; s < 8*NC; s += 256) {
        int ol = s >> 6, j = s & 63;
        int o = og*8 + ol;
        wsm[ol][j] = g_Dend[b*NC + j] * g_Err2[((long)b*NC + j)*DIM + o];
    }
    __syncthreads();
    float Ce = g_Cend[b];
    int ol = tid >> 5, lane = tid & 31;
    int o = og*8 + ol;
    float acc[16];
    #pragma unroll
    for (int k = 0; k < 16; k++) acc[k] = 0.f;
    for (int j = 0; j < NC; j++) {
        float wv = wsm[ol][j];
        const float* krow = &g_kmean[((long)b*NC + j)*DIM];
        #pragma unroll
        for (int k = 0; k < 16; k++) acc[k] += wv * krow[lane + 32*k];
    }
    float* orow = out + ((long)b*DIM + o)*DIM;
    const float* m0row = M0 + (long)o*DIM;
    #pragma unroll
    for (int k = 0; k < 16; k++) {
        int i = lane + 32*k;
        orow[i] = Ce * m0row[i] + acc[k];
    }
}

// ---------------- host entry ----------------
extern "C" void kernel_launch(void* const* d_in, const int* in_sizes, int n_in,
                              void* d_out, int out_size) {
    const float* x         = (const float*)d_in[0];
    const float* M0        = (const float*)d_in[1];
    const float* eta_raw   = (const float*)d_in[2];
    const float* alpha_raw = (const float*)d_in[3];
    const float* gate_w    = (const float*)d_in[4];
    const float* gate_b    = (const float*)d_in[5];
    const float* w1        = (const float*)d_in[6];
    const float* w2        = (const float*)d_in[7];
    float* out = (float*)d_out;

    float *EF, *Cout, *Wm;
    __half *xF, *Y0F, *ukF, *M0F, *w1F, *w2F, *errF, *TmF, *outF, *hidF;
    cudaGetSymbolAddress((void**)&EF,   g_EF);
    cudaGetSymbolAddress((void**)&Cout, g_Cout);
    cudaGetSymbolAddress((void**)&Wm,   g_W);
    cudaGetSymbolAddress((void**)&xF,   g_xF);
    cudaGetSymbolAddress((void**)&Y0F,  g_Y0F);
    cudaGetSymbolAddress((void**)&ukF,  g_ukF);
    cudaGetSymbolAddress((void**)&M0F,  g_M0F);
    cudaGetSymbolAddress((void**)&w1F,  g_w1F);
    cudaGetSymbolAddress((void**)&w2F,  g_w2F);
    cudaGetSymbolAddress((void**)&errF, g_errF);
    cudaGetSymbolAddress((void**)&TmF,  g_TmF);
    cudaGetSymbolAddress((void**)&outF, g_outF);
    cudaGetSymbolAddress((void**)&hidF, g_hidF);

    const long vsz = (long)BATCH*SEQ*DIM;
    const long msz = (long)BATCH*DIM*DIM;
    const bool wantM = ((long)out_size >= vsz + msz);

    // 1. frob
    frob_kernel<<<1, 512>>>(M0);
    // 2. prep (emits xF)
    prep_kernel<<<BATCH*NC, 256>>>(x, gate_w, gate_b);
    // 3. conv(M0)
    conv_kernel<<<(DIM*DIM/4 + 255)/256, 256>>>(M0, M0F, DIM*DIM/4);
    // 4. BIG: Y0F = half(x @ M0^T)   (epi8) <-- profiled slot
    launch_tgemm<128>(xF, M0F, 0, Y0F, 0, 0, 0,
                      BATCH*SEQ, DIM, DIM, 1, 0, 0, 0, 0, 0, 0, 0, 8);
    // 5-6. weight conversions
    conv_kernel<<<(DIM*DIM/4 + 255)/256, 256>>>(w1, w1F, DIM*DIM/4);
    conv_kernel<<<(DIM*DIM/4 + 255)/256, 256>>>(w2, w2F, DIM*DIM/4);
    // 7. Gram
    gram_kernel<<<dim3(NC, BATCH), 256>>>();
    // 8. EF = [u;kmean] @ M0^T   (epi0 fp32)
    launch_tgemm<128>(ukF, M0F, EF, 0, 0, 0, 0,
                      2*BATCH*NC, DIM, DIM, 1, 0, 0, 0, 0, 0, 0, 0, 0);
    // 9. sequential scan
    scan_kernel<<<BATCH, 512>>>(eta_raw, alpha_raw);
    // 10. Err transpose + fp16
    errsplit_kernel<<<dim3(DIM/32, NC/32, BATCH), dim3(32, 8)>>>();
    // 11. Tmat = (x @ kmean^T) * W   (epi4 -> TmF fp16)
    launch_tgemm<64>(xF, ukF + (long)BATCH*NC*DIM, 0, TmF, 0, 0, Wm,
                     SEQ, NC, DIM, BATCH,
                     (long)SEQ*DIM, (long)NC*DIM, 0, (long)SEQ*NC, 0, 0, (long)NC*NC, 4);
    // 12. outF = half(Tmat @ ErrT^T + Cout*Y0F)  (epi6)
    launch_tgemm<128>(TmF, errF, 0, outF, Y0F, Cout, 0,
                      SEQ, DIM, NC, BATCH,
                      (long)SEQ*NC, (long)DIM*NC, 0, (long)SEQ*DIM,
                      (long)SEQ*DIM, (long)NC, 0, 6);
    // 13. hidden = silu(out @ w1^T) -> hidF   (epi2)
    launch_tgemm<128>(outF, w1F, 0, hidF, 0, 0, 0,
                      BATCH*SEQ, DIM, DIM, 1, 0, 0, 0, 0, 0, 0, 0, 2);
    // 14. v_hat = hidden @ w2^T + outF   (epi7, fp32 to d_out)
    launch_tgemm<128>(hidF, w2F, out, 0, outF, 0, 0,
                      BATCH*SEQ, DIM, DIM, 1, 0, 0, (long)SEQ*DIM, 0,
                      0, 0, 0, 7);
    // 15. M_final
    if (wantM) {
        mfinal_kernel<<<dim3(64, BATCH), 256>>>(M0, out + vsz);
    }
}

// round 9
// speedup vs baseline: 1.0836x; 1.0836x over previous
#include <cuda_runtime.h>
#include <cuda_fp16.h>
#include <math.h>
#include <stdint.h>

#define BATCH 16
#define SEQ   4096
#define DIM   512
#define CH    64
#define NC    64

#define MAX_LR_C    0.2f
#define MIN_DECAY_C 0.5f
#define MAX_NORM_C  30.0f
#define NORM_EPS_C  1e-5f

// ---------------- scratch (static device globals) ----------------
__device__ float g_kmean[BATCH*NC*DIM];
__device__ float g_u[BATCH*NC*DIM];
__device__ float g_EF[2*BATCH*NC*DIM];
__device__ float g_KU[BATCH*NC*NC];
__device__ float g_KK[BATCH*NC*NC];
__device__ float g_gate[BATCH*NC];
__device__ float g_Cout[BATCH*NC];
__device__ float g_W[BATCH*NC*NC];
__device__ float g_Err2[BATCH*NC*DIM];          // [b][t][i]
__device__ float g_S[(long)BATCH*SEQ*NC];       // fp32 x@kmean^T (pre W)
__device__ float g_Cend[BATCH];
__device__ float g_Dend[BATCH*NC];
__device__ float g_fro2[1];

__device__ __half g_xF[(long)BATCH*SEQ*DIM];
__device__ __half g_Y0F[(long)BATCH*SEQ*DIM];
__device__ __half g_ukF[2*BATCH*NC*DIM];        // u rows then kmean rows
__device__ __half g_M0F[DIM*DIM];
__device__ __half g_w1F[DIM*DIM];
__device__ __half g_w2F[DIM*DIM];
__device__ __half g_errF[BATCH*DIM*NC];         // [b][i][j]
__device__ __half g_TmF[(long)BATCH*SEQ*NC];
__device__ __half g_outF[(long)BATCH*SEQ*DIM];
__device__ __half g_hidF[(long)BATCH*SEQ*DIM];

// ---------------- PTX helpers ----------------
__device__ __forceinline__ uint32_t smem_u32(const void* p) {
    uint32_t a;
    asm("{ .reg .u64 t; cvta.to.shared.u64 t, %1; cvt.u32.u64 %0, t; }" : "=r"(a) : "l"(p));
    return a;
}
#define CP16(dst, src) \
    asm volatile("cp.async.cg.shared.global [%0], [%1], 16;" :: "r"(dst), "l"(src) : "memory")
#define CPCOMMIT() asm volatile("cp.async.commit_group;" ::: "memory")
#define CPWAIT(n)  asm volatile("cp.async.wait_group %0;" :: "n"(n) : "memory")

__device__ __forceinline__ void ldsm4(uint32_t* r, uint32_t addr) {
    asm volatile("ldmatrix.sync.aligned.m8n8.x4.shared.b16 {%0,%1,%2,%3}, [%4];"
        : "=r"(r[0]), "=r"(r[1]), "=r"(r[2]), "=r"(r[3]) : "r"(addr));
}
__device__ __forceinline__ void mma16816(float* c, const uint32_t* a, const uint32_t* b) {
    asm volatile(
        "mma.sync.aligned.m16n8k16.row.col.f32.f16.f16.f32 "
        "{%0,%1,%2,%3}, {%4,%5,%6,%7}, {%8,%9}, {%0,%1,%2,%3};"
        : "+f"(c[0]), "+f"(c[1]), "+f"(c[2]), "+f"(c[3])
        : "r"(a[0]), "r"(a[1]), "r"(a[2]), "r"(a[3]), "r"(b[0]), "r"(b[1]));
}

// =====================================================================
// fp16 tensor-core GEMM: C[M,N] = A[M,K] @ B[N,K]^T
// epi: 0 C=acc | 2 OF=silu(acc) | 6 OF=half(acc + R[t]*Pf) | 7 C=acc+Pf | 8 OF=half(acc)
// =====================================================================
#define PITCH 72

template<int BNv>
__global__ __launch_bounds__(256, 2) void tgemm(
    const __half* __restrict__ A, const __half* __restrict__ B,
    float* __restrict__ C, __half* __restrict__ OF,
    const __half* __restrict__ Pf, const float* __restrict__ Rvec,
    int N, int K,
    long sA, long sB, long sC, long sO, long sP, long sR, int epi)
{
    constexpr int NT   = BNv / 16;
    constexpr int AOFF = 128 * PITCH * 2;
    constexpr int SS   = AOFF + BNv * PITCH * 2;

    extern __shared__ char smraw[];
    const uint32_t sbase = smem_u32(smraw);

    const int tid = threadIdx.x;
    const int wid = tid >> 5, lane = tid & 31;
    const int wm = wid >> 1, wn = wid & 1;
    const int bx = blockIdx.x, by = blockIdx.y, bz = blockIdx.z;
    const int nk = K >> 6;

    const __half* Ab = A + bz*sA + (long)(by*128)*K;
    const __half* Bb = B + bz*sB + (long)(bx*BNv)*K;

    auto stage = [&](int c) {
        const int s = c % 3;
        const uint32_t st = sbase + s*SS;
        const int koff = c*64;
        #pragma unroll
        for (int j = 0; j < 4; ++j) {
            int i = tid + 256*j;
            int r = i >> 3, v = i & 7;
            CP16(st + (uint32_t)(r*PITCH + v*8)*2, Ab + (long)r*K + koff + v*8);
        }
        #pragma unroll
        for (int j = 0; j < BNv/32; ++j) {
            int i = tid + 256*j;
            int r = i >> 3, v = i & 7;
            CP16(st + AOFF + (uint32_t)(r*PITCH + v*8)*2, Bb + (long)r*K + koff + v*8);
        }
        CPCOMMIT();
    };

    float acc[2][NT][4];
    #pragma unroll
    for (int mt = 0; mt < 2; ++mt)
        #pragma unroll
        for (int nt = 0; nt < NT; ++nt)
            #pragma unroll
            for (int q = 0; q < 4; ++q) acc[mt][nt][q] = 0.f;

    const int arow  = wm*32 + (lane & 15);
    const int acolh = (lane >> 4) * 8;
    const int brow  = wn*(BNv/2) + (lane & 7) + ((lane & 16) ? 8 : 0);
    const int bcolh = (lane & 8) ? 8 : 0;

    uint32_t ah[2][4], bfr[NT][2];

    stage(0);
    if (nk > 1) stage(1);
    for (int c = 0; c < nk; ++c) {
        if (c + 1 < nk) CPWAIT(1); else CPWAIT(0);
        __syncthreads();
        if (c + 2 < nk) stage(c + 2);

        const uint32_t st  = sbase + (c % 3)*SS;
        const uint32_t aB = st, bB = st + AOFF;

        #pragma unroll
        for (int kk = 0; kk < 4; ++kk) {
            #pragma unroll
            for (int mt = 0; mt < 2; ++mt) {
                uint32_t off = (uint32_t)((arow + mt*16)*PITCH + kk*16 + acolh)*2;
                ldsm4(ah[mt], aB + off);
            }
            #pragma unroll
            for (int p = 0; p < NT/2; ++p) {
                uint32_t off = (uint32_t)((brow + p*16)*PITCH + kk*16 + bcolh)*2;
                uint32_t r4[4];
                ldsm4(r4, bB + off);
                bfr[2*p][0]=r4[0]; bfr[2*p][1]=r4[1];
                bfr[2*p+1][0]=r4[2]; bfr[2*p+1][1]=r4[3];
            }
            #pragma unroll
            for (int mt = 0; mt < 2; ++mt)
                #pragma unroll
                for (int nt = 0; nt < NT; ++nt)
                    mma16816(acc[mt][nt], ah[mt], bfr[nt]);
        }
    }

    // ---------------- epilogue ----------------
    const int g2 = lane >> 2, tq = lane & 3;
    #pragma unroll
    for (int mt = 0; mt < 2; ++mt)
        #pragma unroll
        for (int rh = 0; rh < 2; ++rh) {
            const long mg = (long)by*128 + wm*32 + mt*16 + rh*8 + g2;
            float rs = 0.f;
            if (epi == 6) rs = Rvec[bz*sR + (mg >> 6)];
            #pragma unroll
            for (int nt = 0; nt < NT; ++nt) {
                const int col = bx*BNv + wn*(BNv/2) + nt*8 + 2*tq;
                float v0 = acc[mt][nt][rh*2 + 0];
                float v1 = acc[mt][nt][rh*2 + 1];
                const long cofs = mg*(long)N + col;
                if (epi == 6) {
                    __half2 q = *(const __half2*)(Pf + bz*sP + cofs);
                    v0 += rs*__half2float(q.x); v1 += rs*__half2float(q.y);
                } else if (epi == 2) {
                    v0 = v0 / (1.f + expf(-v0));
                    v1 = v1 / (1.f + expf(-v1));
                } else if (epi == 7) {
                    __half2 q = *(const __half2*)(Pf + bz*sP + cofs);
                    v0 += __half2float(q.x); v1 += __half2float(q.y);
                }
                if (epi == 0 || epi == 7)
                    *(float2*)(C + bz*sC + cofs) = make_float2(v0, v1);
                if (epi == 2 || epi == 6 || epi == 8) {
                    __half2 hh;
                    hh.x = __float2half_rn(v0);
                    hh.y = __float2half_rn(v1);
                    *(__half2*)(OF + bz*sO + cofs) = hh;
                }
            }
        }
}

template<int BNv>
static void launch_tgemm(cudaStream_t st,
                         const __half* A, const __half* B,
                         float* C, __half* OF,
                         const __half* Pf, const float* Rvec,
                         int M, int N, int K, int batch,
                         long sA, long sB, long sC, long sO, long sP, long sR, int epi)
{
    int smb = 3 * (128*PITCH*2 + BNv*PITCH*2);
    cudaFuncSetAttribute(tgemm<BNv>, cudaFuncAttributeMaxDynamicSharedMemorySize, smb);
    dim3 g(N/BNv, M/128, batch);
    tgemm<BNv><<<g, 256, smb, st>>>(A, B, C, OF, Pf, Rvec,
                                    N, K, sA, sB, sC, sO, sP, sR, epi);
}

// ---------------- K0: ||M0||_F^2 ----------------
__global__ void frob_kernel(const float* __restrict__ M0) {
    __shared__ float sbuf[32];
    float s = 0.f;
    for (int i = threadIdx.x; i < DIM*DIM; i += blockDim.x) { float v = M0[i]; s += v*v; }
    #pragma unroll
    for (int o = 16; o; o >>= 1) s += __shfl_down_sync(0xffffffffu, s, o);
    int w = threadIdx.x >> 5, l = threadIdx.x & 31;
    if (l == 0) sbuf[w] = s;
    __syncthreads();
    if (w == 0) {
        s = (l < (int)(blockDim.x >> 5)) ? sbuf[l] : 0.f;
        #pragma unroll
        for (int o = 16; o; o >>= 1) s += __shfl_down_sync(0xffffffffu, s, o);
        if (l == 0) g_fro2[0] = s;
    }
}

// ---------------- K1: prep with smem chunk cache (512 thr, 128KB smem) ----------------
__global__ __launch_bounds__(512) void prep_kernel(const float* __restrict__ x,
                                                   const float* __restrict__ gate_w,
                                                   const float* __restrict__ gate_b) {
    extern __shared__ float xs[];           // CH*DIM floats = 128KB
    __shared__ float rinv[CH];
    __shared__ float sred[16];
    int bt = blockIdx.x;
    int tid = threadIdx.x, w = tid >> 5, l = tid & 31;
    const float4* src = (const float4*)(x + (long)bt * CH * DIM);

    // load chunk to smem + emit fp16 x
    for (int i = tid; i < CH*DIM/4; i += 512) {
        float4 v = src[i];
        ((float4*)xs)[i] = v;
        union { __half a[4]; uint2 u; } p;
        p.a[0] = __float2half_rn(v.x); p.a[1] = __float2half_rn(v.y);
        p.a[2] = __float2half_rn(v.z); p.a[3] = __float2half_rn(v.w);
        ((uint2*)(g_xF + (long)bt*CH*DIM))[i] = p.u;
    }
    __syncthreads();

    // row norms
    for (int r = w; r < CH; r += 16) {
        float s = 0.f;
        #pragma unroll 4
        for (int i = l; i < DIM; i += 32) { float v = xs[r*DIM + i]; s += v*v; }
        #pragma unroll
        for (int o = 16; o; o >>= 1) s += __shfl_down_sync(0xffffffffu, s, o);
        if (l == 0) rinv[r] = 1.f / fmaxf(sqrtf(s), NORM_EPS_C);
    }
    __syncthreads();

    // column pass: one column per thread
    int i = tid;
    float sx = 0.f, sk = 0.f;
    #pragma unroll 8
    for (int r = 0; r < CH; r++) {
        float v = xs[r*DIM + i];
        sx += v;
        sk += v * rinv[r];
    }
    float km = sk * (1.f/CH);
    float uv = sx * (1.f/CH) - km;
    long ru = (long)bt*DIM + i;
    long rk = (long)(BATCH*NC + bt)*DIM + i;
    g_kmean[ru] = km;
    g_u[ru]     = uv;
    g_ukF[ru] = __float2half_rn(uv);
    g_ukF[rk] = __float2half_rn(km);

    float gpart = km * gate_w[i];
    #pragma unroll
    for (int o = 16; o; o >>= 1) gpart += __shfl_down_sync(0xffffffffu, gpart, o);
    if (l == 0) sred[w] = gpart;
    __syncthreads();
    if (tid == 0) {
        float g = 0.f;
        #pragma unroll
        for (int k = 0; k < 16; k++) g += sred[k];
        g_gate[bt] = 1.f / (1.f + expf(-(g + gate_b[0])));
    }
}

// ---------------- K2: Gram matrices ----------------
__global__ __launch_bounds__(256) void gram_kernel() {
    int t = blockIdx.x, b = blockIdx.y;
    __shared__ float su[DIM], sk[DIM];
    int tid = threadIdx.x;
    for (int i = tid; i < DIM; i += 256) {
        su[i] = g_u[((long)b*NC + t)*DIM + i];
        sk[i] = g_kmean[((long)b*NC + t)*DIM + i];
    }
    __syncthreads();
    int w = tid >> 5, l = tid & 31;
    for (int j = w; j < NC; j += 8) {
        const float* kj = &g_kmean[((long)b*NC + j)*DIM];
        float pu = 0.f, pk = 0.f;
        for (int i = l; i < DIM; i += 32) {
            float kv = kj[i];
            pu += kv * su[i];
            pk += kv * sk[i];
        }
        #pragma unroll
        for (int o = 16; o; o >>= 1) {
            pu += __shfl_down_sync(0xffffffffu, pu, o);
            pk += __shfl_down_sync(0xffffffffu, pk, o);
        }
        if (l == 0) {
            g_KU[((long)b*NC + t)*NC + j] = pu;
            g_KK[((long)b*NC + t)*NC + j] = pk;
        }
    }
}

// ---------------- K5: sequential scan, err history in SMEM ----------------
__global__ __launch_bounds__(512) void scan_kernel(const float* __restrict__ eta_raw,
                                                   const float* __restrict__ alpha_raw) {
    extern __shared__ float errS[];         // NC*DIM floats = 128KB
    __shared__ float sD[NC], swE[NC], swM[NC];
    __shared__ float sred[64];
    __shared__ float sC, sFro2, sSA, sSD;
    int b = blockIdx.x;
    int tid = threadIdx.x;

    if (tid == 0) { sC = 1.f; sFro2 = g_fro2[0]; }
    if (tid < NC) sD[tid] = 0.f;
    float eta   = (1.f / (1.f + expf(-eta_raw[0]))) * MAX_LR_C;
    float alpha = MIN_DECAY_C + (1.f / (1.f + expf(-alpha_raw[0]))) * (1.f - MIN_DECAY_C);
    __syncthreads();

    for (int t = 0; t < NC; t++) {
        long btn = (long)(b*NC + t)*NC;
        if (tid < NC) {
            float Dv = sD[tid];
            bool act = tid < t;
            g_W[btn + tid] = act ? Dv : 0.f;
            swE[tid] = act ? Dv * g_KU[btn + tid] : 0.f;
            swM[tid] = act ? Dv * g_KK[btn + tid] : 0.f;
        }
        if (tid == 0) g_Cout[b*NC + t] = sC;
        __syncthreads();

        float C = sC;
        float e  = C * g_EF[(long)(b*NC + t)*DIM + tid];
        float mk = C * g_EF[(long)(BATCH*NC + b*NC + t)*DIM + tid];
        #pragma unroll 4
        for (int j = 0; j < t; j++) {
            float er = errS[j*DIM + tid];
            e  += swE[j] * er;
            mk += swM[j] * er;
        }
        errS[t*DIM + tid] = e;

        float r1 = e * mk, r2 = e * e;
        #pragma unroll
        for (int o = 16; o; o >>= 1) {
            r1 += __shfl_down_sync(0xffffffffu, r1, o);
            r2 += __shfl_down_sync(0xffffffffu, r2, o);
        }
        int w = tid >> 5, l = tid & 31;
        __syncthreads();
        if (l == 0) { sred[w] = r1; sred[32 + w] = r2; }
        __syncthreads();
        if (tid == 0) {
            float edm = 0.f, en2 = 0.f;
            #pragma unroll
            for (int k = 0; k < 16; k++) { edm += sred[k]; en2 += sred[32 + k]; }
            float g = g_gate[b*NC + t];
            float a = g*alpha + 1.f - g;
            float d = g*eta;
            float ktt = g_KK[btn + t];
            float fro2 = a*a*sFro2 + 2.f*a*d*edm + d*d*en2*ktt;
            float fro = sqrtf(fro2);
            float s = fminf(MAX_NORM_C / (fro + 1e-6f), 1.f);
            sSA = s*a; sSD = s*d;
            sFro2 = s*s*fro2;
            sC = sC * s * a;
        }
        __syncthreads();
        if (tid < t)  sD[tid] *= sSA;
        if (tid == t) sD[tid]  = sSD;
        __syncthreads();
    }
    if (tid == 0) g_Cend[b] = sC;
    if (tid < NC) g_Dend[b*NC + tid] = sD[tid];
    // write back err history
    for (int t = 0; t < NC; t++)
        g_Err2[((long)b*NC + t)*DIM + tid] = errS[t*DIM + tid];
}

// ---------------- transpose + fp16: Err2[b][t][i] -> errF[b][i][j] ----------------
__global__ void errsplit_kernel() {
    __shared__ float tile[32][33];
    int b  = blockIdx.z;
    int i0 = blockIdx.x * 32;
    int j0 = blockIdx.y * 32;
    int tx = threadIdx.x, ty = threadIdx.y;
    for (int jj = ty; jj < 32; jj += 8)
        tile[jj][tx] = g_Err2[((long)b*NC + j0 + jj)*DIM + i0 + tx];
    __syncthreads();
    for (int ii = ty; ii < 32; ii += 8) {
        float v = tile[tx][ii];
        long o = ((long)b*DIM + i0 + ii)*NC + j0 + tx;
        g_errF[o] = __float2half_rn(v);
    }
}

// ---------------- wscale: TmF = half(S * W) ----------------
__global__ void wscale_kernel() {
    long idx2 = (long)blockIdx.x * 256 + threadIdx.x;
    if (idx2 >= (long)BATCH*SEQ*NC/2) return;
    long e = idx2 * 2;
    int j = (int)(e & 63);
    long r = e >> 6;
    int b = (int)(r >> 12);
    int t = (int)((r >> 6) & 63);
    float2 sv = ((const float2*)g_S)[idx2];
    const float* wr = &g_W[((long)(b*NC) + t)*NC + j];
    __half2 h;
    h.x = __float2half_rn(sv.x * wr[0]);
    h.y = __float2half_rn(sv.y * wr[1]);
    ((__half2*)g_TmF)[idx2] = h;
}

// ---------------- fp32 -> fp16 ----------------
__global__ void conv_kernel(const float* __restrict__ s, __half* __restrict__ F, long n4) {
    long i = (long)blockIdx.x * 256 + threadIdx.x;
    if (i >= n4) return;
    float4 x = ((const float4*)s)[i];
    union { __half a[4]; uint2 u; } p;
    p.a[0] = __float2half_rn(x.x);
    p.a[1] = __float2half_rn(x.y);
    p.a[2] = __float2half_rn(x.z);
    p.a[3] = __float2half_rn(x.w);
    ((uint2*)F)[i] = p.u;
}

// ---------------- M_final ----------------
__global__ __launch_bounds__(256) void mfinal_kernel(const float* __restrict__ M0,
                                                     float* __restrict__ out) {
    int og = blockIdx.x;
    int b  = blockIdx.y;
    int tid = threadIdx.x;
    __shared__ float wsm[8][NC];
    for (int s = tid; s < 8*NC; s += 256) {
        int ol = s >> 6, j = s & 63;
        int o = og*8 + ol;
        wsm[ol][j] = g_Dend[b*NC + j] * g_Err2[((long)b*NC + j)*DIM + o];
    }
    __syncthreads();
    float Ce = g_Cend[b];
    int ol = tid >> 5, lane = tid & 31;
    int o = og*8 + ol;
    float acc[16];
    #pragma unroll
    for (int k = 0; k < 16; k++) acc[k] = 0.f;
    for (int j = 0; j < NC; j++) {
        float wv = wsm[ol][j];
        const float* krow = &g_kmean[((long)b*NC + j)*DIM];
        #pragma unroll
        for (int k = 0; k < 16; k++) acc[k] += wv * krow[lane + 32*k];
    }
    float* orow = out + ((long)b*DIM + o)*DIM;
    const float* m0row = M0 + (long)o*DIM;
    #pragma unroll
    for (int k = 0; k < 16; k++) {
        int i = lane + 32*k;
        orow[i] = Ce * m0row[i] + acc[k];
    }
}

// ---------------- host entry ----------------
extern "C" void kernel_launch(void* const* d_in, const int* in_sizes, int n_in,
                              void* d_out, int out_size) {
    const float* x         = (const float*)d_in[0];
    const float* M0        = (const float*)d_in[1];
    const float* eta_raw   = (const float*)d_in[2];
    const float* alpha_raw = (const float*)d_in[3];
    const float* gate_w    = (const float*)d_in[4];
    const float* gate_b    = (const float*)d_in[5];
    const float* w1        = (const float*)d_in[6];
    const float* w2        = (const float*)d_in[7];
    float* out = (float*)d_out;

    float *EF, *Cout, *Sf;
    __half *xF, *Y0F, *ukF, *M0F, *w1F, *w2F, *errF, *TmF, *outF, *hidF;
    cudaGetSymbolAddress((void**)&EF,   g_EF);
    cudaGetSymbolAddress((void**)&Cout, g_Cout);
    cudaGetSymbolAddress((void**)&Sf,   g_S);
    cudaGetSymbolAddress((void**)&xF,   g_xF);
    cudaGetSymbolAddress((void**)&Y0F,  g_Y0F);
    cudaGetSymbolAddress((void**)&ukF,  g_ukF);
    cudaGetSymbolAddress((void**)&M0F,  g_M0F);
    cudaGetSymbolAddress((void**)&w1F,  g_w1F);
    cudaGetSymbolAddress((void**)&w2F,  g_w2F);
    cudaGetSymbolAddress((void**)&errF, g_errF);
    cudaGetSymbolAddress((void**)&TmF,  g_TmF);
    cudaGetSymbolAddress((void**)&outF, g_outF);
    cudaGetSymbolAddress((void**)&hidF, g_hidF);

    const long vsz = (long)BATCH*SEQ*DIM;
    const long msz = (long)BATCH*DIM*DIM;
    const bool wantM = ((long)out_size >= vsz + msz);

    // one-time side stream + events (created on the non-captured correctness call)
    static cudaStream_t sSide = 0;
    static cudaEvent_t evFork = 0, evJoin = 0;
    if (!sSide) {
        cudaStreamCreateWithFlags(&sSide, cudaStreamNonBlocking);
        cudaEventCreateWithFlags(&evFork, cudaEventDisableTiming);
        cudaEventCreateWithFlags(&evJoin, cudaEventDisableTiming);
    }

    cudaFuncSetAttribute(prep_kernel, cudaFuncAttributeMaxDynamicSharedMemorySize, CH*DIM*4);
    cudaFuncSetAttribute(scan_kernel, cudaFuncAttributeMaxDynamicSharedMemorySize, NC*DIM*4);

    // ---- main stream: head ----
    frob_kernel<<<1, 512>>>(M0);
    prep_kernel<<<BATCH*NC, 512, CH*DIM*4>>>(x, gate_w, gate_b);
    conv_kernel<<<(DIM*DIM/4 + 255)/256, 256>>>(M0, M0F, DIM*DIM/4);
    cudaEventRecord(evFork, 0);

    // ---- side stream: the two big independent GEMMs ----
    cudaStreamWaitEvent(sSide, evFork, 0);
    launch_tgemm<128>(sSide, xF, M0F, 0, Y0F, 0, 0,
                      BATCH*SEQ, DIM, DIM, 1, 0, 0, 0, 0, 0, 0, 8);   // Y0F = half(x@M0^T)
    launch_tgemm<64>(sSide, xF, ukF + (long)BATCH*NC*DIM, Sf, 0, 0, 0,
                     SEQ, NC, DIM, BATCH,
                     (long)SEQ*DIM, (long)NC*DIM, (long)SEQ*NC, 0, 0, 0, 0);  // S = x@kmean^T
    cudaEventRecord(evJoin, sSide);

    // ---- main stream: narrow chain (overlaps side) ----
    conv_kernel<<<(DIM*DIM/4 + 255)/256, 256>>>(w1, w1F, DIM*DIM/4);
    conv_kernel<<<(DIM*DIM/4 + 255)/256, 256>>>(w2, w2F, DIM*DIM/4);
    gram_kernel<<<dim3(NC, BATCH), 256>>>();
    launch_tgemm<128>(0, ukF, M0F, EF, 0, 0, 0,
                      2*BATCH*NC, DIM, DIM, 1, 0, 0, 0, 0, 0, 0, 0);  // EF
    scan_kernel<<<BATCH, 512, NC*DIM*4>>>(eta_raw, alpha_raw);
    errsplit_kernel<<<dim3(DIM/32, NC/32, BATCH), dim3(32, 8)>>>();

    // ---- join ----
    cudaStreamWaitEvent(0, evJoin, 0);
    {
        long n2 = (long)BATCH*SEQ*NC/2;
        wscale_kernel<<<(unsigned)((n2 + 255)/256), 256>>>();
    }
    // outF = half(Tm @ Err^T + Cout*Y0F)
    launch_tgemm<128>(0, TmF, errF, 0, outF, Y0F, Cout,
                      SEQ, DIM, NC, BATCH,
                      (long)SEQ*NC, (long)DIM*NC, 0, (long)SEQ*DIM,
                      (long)SEQ*DIM, (long)NC, 6);
    // hidden = silu(out @ w1^T)
    launch_tgemm<128>(0, outF, w1F, 0, hidF, 0, 0,
                      BATCH*SEQ, DIM, DIM, 1, 0, 0, 0, 0, 0, 0, 2);
    // v_hat = hidden @ w2^T + outF
    launch_tgemm<128>(0, hidF, w2F, out, 0, outF, 0,
                      BATCH*SEQ, DIM, DIM, 1, 0, 0, (long)SEQ*DIM, 0, 0, 0, 7);
    if (wantM) {
        mfinal_kernel<<<dim3(64, BATCH), 256>>>(M0, out + vsz);
    }
}